// round 15
// baseline (speedup 1.0000x reference)
#include <cuda_runtime.h>
#include <cstdint>

#define BATCH 4
#define SEQ   2048
#define DSEQ  1024
#define HEADS 16
#define DHEAD 64
#define DINNER 1024
#define MROWS (BATCH*SEQ)   // 8192
#define NQKV  (3*DINNER)    // 3072

// Scratch (allocation-free: __device__ globals)
__device__ float g_Q[BATCH * HEADS * SEQ * DHEAD];
__device__ float g_K[BATCH * HEADS * SEQ * DHEAD];
__device__ float g_V[BATCH * HEADS * SEQ * DHEAD];
__device__ float g_AO[MROWS * DINNER];
// tf32-pre-rounded operand copies
__device__ float g_X[MROWS * DSEQ];
__device__ float g_Wq[NQKV * DSEQ];
__device__ float g_Wo[DSEQ * DINNER];

__device__ __forceinline__ float f2tf(float f) {
    unsigned u;
    asm("cvt.rna.tf32.f32 %0, %1;" : "=r"(u) : "f"(f));
    return __uint_as_float(u);
}
__device__ __forceinline__ void mma_tf32(float c[4],
                                         unsigned a0, unsigned a1, unsigned a2, unsigned a3,
                                         unsigned b0, unsigned b1) {
    asm volatile(
        "mma.sync.aligned.m16n8k8.row.col.f32.tf32.tf32.f32 "
        "{%0,%1,%2,%3},{%4,%5,%6,%7},{%8,%9},{%0,%1,%2,%3};"
        : "+f"(c[0]), "+f"(c[1]), "+f"(c[2]), "+f"(c[3])
        : "r"(a0), "r"(a1), "r"(a2), "r"(a3), "r"(b0), "r"(b1));
}
#define FB(x) __float_as_uint(x)

__device__ __forceinline__ unsigned smem_u32(const void* p) {
    unsigned a;
    asm("{ .reg .u64 t; cvta.to.shared.u64 t, %1; cvt.u32.u64 %0, t; }"
        : "=r"(a) : "l"(p));
    return a;
}
__device__ __forceinline__ void cp16(unsigned dst, const float* src) {
    asm volatile("cp.async.cg.shared.global [%0], [%1], 16;"
                 :: "r"(dst), "l"(src) : "memory");
}
#define CP_COMMIT() asm volatile("cp.async.commit_group;" ::: "memory")
#define CP_WAIT1()  asm volatile("cp.async.wait_group 1;" ::: "memory")

// ---------------------------------------------------------------------
// Pre-convert inputs to tf32-rounded copies.
// ---------------------------------------------------------------------
__global__ __launch_bounds__(256) void preconvert(const float* __restrict__ x,
                                                  const float* __restrict__ wq,
                                                  const float* __restrict__ wo) {
    const int idx = (blockIdx.x * 256 + threadIdx.x) * 4;
    const int NX = MROWS * DSEQ, NQ = NQKV * DSEQ, NO = DSEQ * DINNER;
    if (idx < NX) {
        float4 v = *(const float4*)(x + idx);
        *(float4*)(g_X + idx) = make_float4(f2tf(v.x), f2tf(v.y), f2tf(v.z), f2tf(v.w));
    } else if (idx < NX + NQ) {
        int i = idx - NX;
        float4 v = *(const float4*)(wq + i);
        *(float4*)(g_Wq + i) = make_float4(f2tf(v.x), f2tf(v.y), f2tf(v.z), f2tf(v.w));
    } else if (idx < NX + NQ + NO) {
        int i = idx - NX - NQ;
        float4 v = *(const float4*)(wo + i);
        *(float4*)(g_Wo + i) = make_float4(f2tf(v.x), f2tf(v.y), f2tf(v.z), f2tf(v.w));
    }
}
#define PRECONV_ELEMS (MROWS * DSEQ + NQKV * DSEQ + DSEQ * DINNER)

// ---------------------------------------------------------------------
// GEMM (round-14): BM=BN=128, BK=16, 512 thr, 16 warps (4m x 4n), warp
// tile 32x32, GST=20, NSTG=5 ring, barrier every 2 k-tiles, 2 CTAs/SM.
// mode 0: g_X @ g_Wq^T -> Q/K/V.  mode 1: g_AO @ g_Wo^T + bias.
// ---------------------------------------------------------------------
#define GST 20
#define NSTG 5
#define STGF (128 * GST)
#define GNIT 64
#define GEMM_SMEM_BYTES (2 * NSTG * STGF * 4)   // 102400

__device__ __forceinline__ void g_mma_tile(const float* As_, const float* Bs_,
                                           float c[2][4][4],
                                           int wm, int wn, int g, int tg) {
#pragma unroll
    for (int kk = 0; kk < 2; kk++) {
        const int k = kk * 8;
        unsigned a[2][4], b[4][2];
#pragma unroll
        for (int mt = 0; mt < 2; mt++) {
            const float* ap = &As_[(wm * 32 + mt * 16 + g) * GST + k + tg];
            a[mt][0] = FB(ap[0]);
            a[mt][1] = FB(ap[8 * GST]);
            a[mt][2] = FB(ap[4]);
            a[mt][3] = FB(ap[8 * GST + 4]);
        }
#pragma unroll
        for (int nt = 0; nt < 4; nt++) {
            const float* bp = &Bs_[(wn * 32 + nt * 8 + g) * GST + k + tg];
            b[nt][0] = FB(bp[0]);
            b[nt][1] = FB(bp[4]);
        }
#pragma unroll
        for (int mt = 0; mt < 2; mt++)
#pragma unroll
            for (int nt = 0; nt < 4; nt++)
                mma_tf32(c[mt][nt], a[mt][0], a[mt][1], a[mt][2], a[mt][3],
                         b[nt][0], b[nt][1]);
    }
}

__global__ __launch_bounds__(512, 2) void gemm_kernel(
    const float* __restrict__ bias, float* __restrict__ out, int mode)
{
    extern __shared__ float smf[];
    float* As = smf;
    float* Bs = smf + NSTG * STGF;

    const int t    = threadIdx.x;
    const int lane = t & 31;
    const int wp   = t >> 5;
    const int g    = lane >> 2;
    const int tg   = lane & 3;
    const int wm   = wp & 3;
    const int wn   = wp >> 2;
    const int m0   = blockIdx.y * 128;
    const int n0   = blockIdx.x * 128;

    const float* A = (mode == 1) ? (const float*)g_AO : (const float*)g_X;
    const float* B = (mode == 1) ? (const float*)g_Wo : (const float*)g_Wq;

    const int row = t >> 2;
    const int kq  = (t & 3) * 4;
    const float* Ag = A + (size_t)(m0 + row) * 1024 + kq;
    const float* Bg = B + (size_t)(n0 + row) * 1024 + kq;
    const unsigned aOff = smem_u32(As) + (unsigned)(row * GST + kq) * 4u;
    const unsigned bOff = smem_u32(Bs) + (unsigned)(row * GST + kq) * 4u;

#pragma unroll
    for (int s = 0; s < 3; s++) {
        const unsigned so = (unsigned)(s * STGF) * 4u;
        cp16(aOff + so, Ag + s * 16);
        cp16(bOff + so, Bg + s * 16);
        CP_COMMIT();
    }

    float c[2][4][4] = {};

    for (int it = 0; it < GNIT; it += 2) {
        CP_WAIT1();
        __syncthreads();
#pragma unroll
        for (int q = 0; q < 2; q++) {
            const int ld = it + 3 + q;
            if (ld < GNIT) {
                const unsigned so = (unsigned)((ld % NSTG) * STGF) * 4u;
                cp16(aOff + so, Ag + ld * 16);
                cp16(bOff + so, Bg + ld * 16);
            }
            CP_COMMIT();
        }
        const int s0 = it % NSTG;
        const int s1 = (it + 1) % NSTG;
        g_mma_tile(As + s0 * STGF, Bs + s0 * STGF, c, wm, wn, g, tg);
        g_mma_tile(As + s1 * STGF, Bs + s1 * STGF, c, wm, wn, g, tg);
    }

    if (mode == 0) {
#pragma unroll
        for (int mt = 0; mt < 2; mt++) {
#pragma unroll
            for (int nt = 0; nt < 4; nt++) {
                int col  = n0 + wn * 32 + nt * 8 + tg * 2;
                int part = col >> 10;
                int h    = (col >> 6) & 15;
                int d    = col & 63;
                float* Tp = (part == 0) ? g_Q : (part == 1) ? g_K : g_V;
                int m  = m0 + wm * 32 + mt * 16 + g;
                int b  = m >> 11, n = m & 2047;
                *(float2*)&Tp[(((size_t)(b * HEADS + h)) * SEQ + n) * DHEAD + d] =
                    make_float2(f2tf(c[mt][nt][0]), f2tf(c[mt][nt][1]));
                int m2 = m + 8;
                int b2 = m2 >> 11, n2 = m2 & 2047;
                *(float2*)&Tp[(((size_t)(b2 * HEADS + h)) * SEQ + n2) * DHEAD + d] =
                    make_float2(f2tf(c[mt][nt][2]), f2tf(c[mt][nt][3]));
            }
        }
    } else {
#pragma unroll
        for (int mt = 0; mt < 2; mt++) {
#pragma unroll
            for (int nt = 0; nt < 4; nt++) {
                int col = n0 + wn * 32 + nt * 8 + tg * 2;
                float bx = bias[col], by = bias[col + 1];
                int m = m0 + wm * 32 + mt * 16 + g;
                *(float2*)&out[(size_t)m * DSEQ + col] =
                    make_float2(c[mt][nt][0] + bx, c[mt][nt][1] + by);
                *(float2*)&out[(size_t)(m + 8) * DSEQ + col] =
                    make_float2(c[mt][nt][2] + bx, c[mt][nt][3] + by);
            }
        }
    }
}

// ---------------------------------------------------------------------
// Flash attention v5: Q hoisted to registers, K/V DOUBLE-BUFFERED.
// Per kv-iter: 1 cp-wait + 2 barriers (was 2 waits + 4 barriers); single
// commit per iter with both K and V of tile i+2; prefetch overlaps the
// entire next-iteration body. smem = 2K + 2V + Ps = 104 KB, 2 CTAs/SM.
// ---------------------------------------------------------------------
#define AQT 68
#define AVT 72
#define KBUF (64 * AQT)
#define VBUF (64 * AVT)
#define ATTN_FLOATS (2*KBUF + 2*VBUF + 128*AQT)
#define ATTN_SMEM_BYTES (ATTN_FLOATS * 4)   // 106496
#define NITER (SEQ / 64)

__global__ __launch_bounds__(128, 2) void attn_kernel() {
    extern __shared__ float sm[];
    float* Ks = sm;                          // 2 x 64*AQT
    float* Vs = sm + 2 * KBUF;               // 2 x 64*AVT
    float* Ps = sm + 2 * KBUF + 2 * VBUF;    // 128*AQT

    const int t    = threadIdx.x;
    const int lane = t & 31;
    const int wp   = t >> 5;
    const int g    = lane >> 2;
    const int tg   = lane & 3;
    const int bh   = blockIdx.y;
    const int q0   = blockIdx.x * 128;

    const size_t base = (size_t)bh * SEQ * DHEAD;
    const float* Qg = g_Q + base;
    const float* Kg = g_K + base;
    const float* Vg = g_V + base;

    const int lj = t >> 1;
    const int lh = (t & 1) * 32;
    const unsigned kDst0 = smem_u32(Ks) + (unsigned)(lj * AQT + lh) * 4u;
    const unsigned vDst0 = smem_u32(Vs) + (unsigned)(lj * AVT + lh) * 4u;
    const float* kSrc = Kg + (size_t)lj * DHEAD + lh;
    const float* vSrc = Vg + (size_t)lj * DHEAD + lh;

    // prologue: tiles 0,1 in flight (one commit each, K+V together)
#pragma unroll
    for (int p = 0; p < 2; p++) {
        const unsigned ko = kDst0 + (unsigned)(p * KBUF) * 4u;
        const unsigned vo = vDst0 + (unsigned)(p * VBUF) * 4u;
        const float* ks = kSrc + (size_t)p * 64 * DHEAD;
        const float* vs = vSrc + (size_t)p * 64 * DHEAD;
#pragma unroll
        for (int q = 0; q < 8; q++) {
            cp16(ko + q * 16u, ks + q * 4);
            cp16(vo + q * 16u, vs + q * 4);
        }
        CP_COMMIT();
    }

    // ---- hoist Q fragments into registers (loop-invariant) ----
    unsigned qa[2][8][4];
#pragma unroll
    for (int mt = 0; mt < 2; mt++) {
        const float* r0 = Qg + (size_t)(q0 + wp * 32 + mt * 16 + g) * DHEAD;
        const float* r1 = r0 + 8 * DHEAD;
#pragma unroll
        for (int kk = 0; kk < 8; kk++) {
            const int k = kk * 8;
            qa[mt][kk][0] = FB(r0[k + tg] * 0.125f);
            qa[mt][kk][1] = FB(r1[k + tg] * 0.125f);
            qa[mt][kk][2] = FB(r0[k + tg + 4] * 0.125f);
            qa[mt][kk][3] = FB(r1[k + tg + 4] * 0.125f);
        }
    }

    float mi[4] = {-1e30f, -1e30f, -1e30f, -1e30f};
    float li[4] = {0.f, 0.f, 0.f, 0.f};
    float of[2][8][4] = {};

    for (int i = 0; i < NITER; i++) {
        CP_WAIT1();          // tile i complete (tile i+1 in flight)
        __syncthreads();     // cross-warp visibility of tile i
        const float* Kb = Ks + (i & 1) * KBUF;
        const float* Vb = Vs + (i & 1) * VBUF;

        // ---- S = Q K^T ----
        float sc[2][8][4] = {};
#pragma unroll
        for (int kk = 0; kk < 8; kk++) {
            const int k = kk * 8;
#pragma unroll
            for (int nt = 0; nt < 8; nt++) {
                const float* bp = &Kb[(nt * 8 + g) * AQT + k + tg];
                unsigned b0 = FB(bp[0]), b1 = FB(bp[4]);
                mma_tf32(sc[0][nt], qa[0][kk][0], qa[0][kk][1], qa[0][kk][2], qa[0][kk][3], b0, b1);
                mma_tf32(sc[1][nt], qa[1][kk][0], qa[1][kk][1], qa[1][kk][2], qa[1][kk][3], b0, b1);
            }
        }

        // ---- online softmax ----
        float mx[4] = {-1e30f, -1e30f, -1e30f, -1e30f};
#pragma unroll
        for (int mt = 0; mt < 2; mt++)
#pragma unroll
            for (int nt = 0; nt < 8; nt++) {
                mx[2*mt]   = fmaxf(mx[2*mt],   fmaxf(sc[mt][nt][0], sc[mt][nt][1]));
                mx[2*mt+1] = fmaxf(mx[2*mt+1], fmaxf(sc[mt][nt][2], sc[mt][nt][3]));
            }
#pragma unroll
        for (int off = 1; off <= 2; off <<= 1)
#pragma unroll
            for (int r = 0; r < 4; r++)
                mx[r] = fmaxf(mx[r], __shfl_xor_sync(0xffffffffu, mx[r], off));
        float al[4], rs[4] = {0.f, 0.f, 0.f, 0.f};
#pragma unroll
        for (int r = 0; r < 4; r++) {
            float mn = fmaxf(mi[r], mx[r]);
            al[r] = __expf(mi[r] - mn);
            mi[r] = mn;
        }
#pragma unroll
        for (int mt = 0; mt < 2; mt++)
#pragma unroll
            for (int nt = 0; nt < 8; nt++) {
                sc[mt][nt][0] = __expf(sc[mt][nt][0] - mi[2*mt]);
                sc[mt][nt][1] = __expf(sc[mt][nt][1] - mi[2*mt]);
                sc[mt][nt][2] = __expf(sc[mt][nt][2] - mi[2*mt+1]);
                sc[mt][nt][3] = __expf(sc[mt][nt][3] - mi[2*mt+1]);
                rs[2*mt]   += sc[mt][nt][0] + sc[mt][nt][1];
                rs[2*mt+1] += sc[mt][nt][2] + sc[mt][nt][3];
            }
#pragma unroll
        for (int off = 1; off <= 2; off <<= 1)
#pragma unroll
            for (int r = 0; r < 4; r++)
                rs[r] += __shfl_xor_sync(0xffffffffu, rs[r], off);
#pragma unroll
        for (int r = 0; r < 4; r++) li[r] = li[r] * al[r] + rs[r];
#pragma unroll
        for (int mt = 0; mt < 2; mt++)
#pragma unroll
            for (int nt = 0; nt < 8; nt++) {
                of[mt][nt][0] *= al[2*mt];   of[mt][nt][1] *= al[2*mt];
                of[mt][nt][2] *= al[2*mt+1]; of[mt][nt][3] *= al[2*mt+1];
            }

        // ---- store P (warp-private rows) ----
#pragma unroll
        for (int mt = 0; mt < 2; mt++)
#pragma unroll
            for (int nt = 0; nt < 8; nt++) {
                *(float2*)&Ps[(wp * 32 + mt * 16 + g) * AQT + nt * 8 + tg * 2] =
                    make_float2(f2tf(sc[mt][nt][0]), f2tf(sc[mt][nt][1]));
                *(float2*)&Ps[(wp * 32 + mt * 16 + g + 8) * AQT + nt * 8 + tg * 2] =
                    make_float2(f2tf(sc[mt][nt][2]), f2tf(sc[mt][nt][3]));
            }
        __syncwarp();

        // ---- O += P V ----
#pragma unroll
        for (int kk = 0; kk < 8; kk++) {
            const int k = kk * 8;
            unsigned a[2][4];
#pragma unroll
            for (int mt = 0; mt < 2; mt++) {
                const float* ap = &Ps[(wp * 32 + mt * 16 + g) * AQT + k + tg];
                a[mt][0] = FB(ap[0]);
                a[mt][1] = FB(ap[8 * AQT]);
                a[mt][2] = FB(ap[4]);
                a[mt][3] = FB(ap[8 * AQT + 4]);
            }
#pragma unroll
            for (int nt = 0; nt < 8; nt++) {
                unsigned b0 = FB(Vb[(k + tg)     * AVT + nt * 8 + g]);
                unsigned b1 = FB(Vb[(k + tg + 4) * AVT + nt * 8 + g]);
                mma_tf32(of[0][nt], a[0][0], a[0][1], a[0][2], a[0][3], b0, b1);
                mma_tf32(of[1][nt], a[1][0], a[1][1], a[1][2], a[1][3], b0, b1);
            }
        }
        __syncthreads();     // all warps done reading buf i&1

        // ---- issue tile i+2 into the freed buffer, single commit ----
        if (i + 2 < NITER) {
            const unsigned ko = kDst0 + (unsigned)((i & 1) * KBUF) * 4u;
            const unsigned vo = vDst0 + (unsigned)((i & 1) * VBUF) * 4u;
            const float* ks = kSrc + (size_t)(i + 2) * 64 * DHEAD;
            const float* vs = vSrc + (size_t)(i + 2) * 64 * DHEAD;
#pragma unroll
            for (int q = 0; q < 8; q++) {
                cp16(ko + q * 16u, ks + q * 4);
                cp16(vo + q * 16u, vs + q * 4);
            }
        }
        CP_COMMIT();         // keep ledger fixed (empty near the end)
    }

    // ---- epilogue: write g_AO tf32-rounded ----
    const int b = bh >> 4;
    const int h = bh & 15;
#pragma unroll
    for (int mt = 0; mt < 2; mt++) {
        const float inv0 = 1.0f / li[2*mt];
        const float inv1 = 1.0f / li[2*mt+1];
        const int row0 = q0 + wp * 32 + mt * 16 + g;
#pragma unroll
        for (int nt = 0; nt < 8; nt++) {
            int d = nt * 8 + tg * 2;
            *(float2*)&g_AO[((size_t)(b * SEQ + row0)) * DINNER + h * 64 + d] =
                make_float2(f2tf(of[mt][nt][0] * inv0), f2tf(of[mt][nt][1] * inv0));
            *(float2*)&g_AO[((size_t)(b * SEQ + row0 + 8)) * DINNER + h * 64 + d] =
                make_float2(f2tf(of[mt][nt][2] * inv1), f2tf(of[mt][nt][3] * inv1));
        }
    }
}

// ---------------------------------------------------------------------
extern "C" void kernel_launch(void* const* d_in, const int* in_sizes, int n_in,
                              void* d_out, int out_size) {
    const float* x     = (const float*)d_in[0];
    const float* w_qkv = (const float*)d_in[1];
    const float* w_out = (const float*)d_in[2];
    const float* b_out = (const float*)d_in[3];
    float* out = (float*)d_out;

    cudaFuncSetAttribute(gemm_kernel, cudaFuncAttributeMaxDynamicSharedMemorySize,
                         GEMM_SMEM_BYTES);
    cudaFuncSetAttribute(attn_kernel, cudaFuncAttributeMaxDynamicSharedMemorySize,
                         ATTN_SMEM_BYTES);

    preconvert<<<(PRECONV_ELEMS / 4 + 255) / 256, 256>>>(x, w_qkv, w_out);
    gemm_kernel<<<dim3(NQKV / 128, MROWS / 128), 512, GEMM_SMEM_BYTES>>>(nullptr, nullptr, 0);
    attn_kernel<<<dim3(SEQ / 128, BATCH * HEADS), 128, ATTN_SMEM_BYTES>>>();
    gemm_kernel<<<dim3(DSEQ / 128, MROWS / 128), 512, GEMM_SMEM_BYTES>>>(b_out, out, 1);
}

// round 16
// speedup vs baseline: 1.0580x; 1.0580x over previous
#include <cuda_runtime.h>
#include <cstdint>

#define BATCH 4
#define SEQ   2048
#define DSEQ  1024
#define HEADS 16
#define DHEAD 64
#define DINNER 1024
#define MROWS (BATCH*SEQ)   // 8192
#define NQKV  (3*DINNER)    // 3072

// Scratch (allocation-free: __device__ globals)
__device__ float g_Q[BATCH * HEADS * SEQ * DHEAD];
__device__ float g_K[BATCH * HEADS * SEQ * DHEAD];
__device__ float g_V[BATCH * HEADS * SEQ * DHEAD];
__device__ float g_AO[MROWS * DINNER];               // PERMUTED k-cols
// tf32-pre-rounded, column-PERMUTED operand copies
__device__ float g_X[MROWS * DSEQ];
__device__ float g_Wq[NQKV * DSEQ];
__device__ float g_Wo[DSEQ * DINNER];

__device__ __forceinline__ float f2tf(float f) {
    unsigned u;
    asm("cvt.rna.tf32.f32 %0, %1;" : "=r"(u) : "f"(f));
    return __uint_as_float(u);
}
__device__ __forceinline__ void mma_tf32(float c[4],
                                         unsigned a0, unsigned a1, unsigned a2, unsigned a3,
                                         unsigned b0, unsigned b1) {
    asm volatile(
        "mma.sync.aligned.m16n8k8.row.col.f32.tf32.tf32.f32 "
        "{%0,%1,%2,%3},{%4,%5,%6,%7},{%8,%9},{%0,%1,%2,%3};"
        : "+f"(c[0]), "+f"(c[1]), "+f"(c[2]), "+f"(c[3])
        : "r"(a0), "r"(a1), "r"(a2), "r"(a3), "r"(b0), "r"(b1));
}
#define FB(x) __float_as_uint(x)

__device__ __forceinline__ unsigned smem_u32(const void* p) {
    unsigned a;
    asm("{ .reg .u64 t; cvta.to.shared.u64 t, %1; cvt.u32.u64 %0, t; }"
        : "=r"(a) : "l"(p));
    return a;
}
__device__ __forceinline__ void cp16(unsigned dst, const float* src) {
    asm volatile("cp.async.cg.shared.global [%0], [%1], 16;"
                 :: "r"(dst), "l"(src) : "memory");
}
#define CP_COMMIT() asm volatile("cp.async.commit_group;" ::: "memory")
#define CP_WAIT2()  asm volatile("cp.async.wait_group 2;" ::: "memory")
#define CP_WAIT1()  asm volatile("cp.async.wait_group 1;" ::: "memory")

// fragment-pair permutation within each 8-col k-group:
// logical c -> (c & ~7) | 2*(c&3) | ((c>>2)&1). Pairs (c, c+4) adjacent.
__device__ __forceinline__ int cperm8(int c) {
    return (c & ~7) | (((c & 3) << 1) | ((c >> 2) & 1));
}

// ---------------------------------------------------------------------
// Pre-convert inputs to tf32-rounded, column-permuted copies.
// Each thread: 4 consecutive logical cols (same 8-group half) ->
// positions base8 + h + {0,2,4,6} where h = (idx>>2)&1.
// ---------------------------------------------------------------------
__global__ __launch_bounds__(256) void preconvert(const float* __restrict__ x,
                                                  const float* __restrict__ wq,
                                                  const float* __restrict__ wo) {
    const int idx = (blockIdx.x * 256 + threadIdx.x) * 4;
    const int NX = MROWS * DSEQ, NQ = NQKV * DSEQ, NO = DSEQ * DINNER;
    const float* src; float* dst; int i;
    if (idx < NX)            { src = x;  dst = g_X;  i = idx; }
    else if (idx < NX + NQ)  { src = wq; dst = g_Wq; i = idx - NX; }
    else if (idx < NX + NQ + NO) { src = wo; dst = g_Wo; i = idx - NX - NQ; }
    else return;
    float4 v = *(const float4*)(src + i);
    const int base = (i & ~7) | ((i >> 2) & 1);
    dst[base + 0] = f2tf(v.x);
    dst[base + 2] = f2tf(v.y);
    dst[base + 4] = f2tf(v.z);
    dst[base + 6] = f2tf(v.w);
}
#define PRECONV_ELEMS (MROWS * DSEQ + NQKV * DSEQ + DSEQ * DINNER)

// ---------------------------------------------------------------------
// GEMM v5: BM=BN=128, BK=16, 512 thr, 16 warps (4m x 4n), warp tile
// 32x32, GST=24 with permuted columns -> ALL fragment loads are LDS.64
// (conflict-free: per phase banks {0-7},{24-31},{16-23},{8-15}).
// 4-stage cp.async (wait_group 2), sync per k-tile. 2 CTAs/SM.
// mode 0: g_X @ g_Wq^T -> Q/K/V (natural).  mode 1: g_AO @ g_Wo^T + bias.
// ---------------------------------------------------------------------
#define GST 24
#define NSTG 4
#define STGF (128 * GST)
#define GNIT 64
#define GEMM_SMEM_BYTES (2 * NSTG * STGF * 4)   // 98304

__device__ __forceinline__ void g_mma_tile(const float* As_, const float* Bs_,
                                           float c[2][4][4],
                                           int wm, int wn, int g, int tg) {
#pragma unroll
    for (int kk = 0; kk < 2; kk++) {
        const int ko = kk * 8 + 2 * tg;
        unsigned a[2][4], b[4][2];
#pragma unroll
        for (int mt = 0; mt < 2; mt++) {
            const float* ap = &As_[(wm * 32 + mt * 16 + g) * GST + ko];
            float2 lo = *(const float2*)ap;
            float2 hi = *(const float2*)(ap + 8 * GST);
            a[mt][0] = FB(lo.x); a[mt][1] = FB(hi.x);
            a[mt][2] = FB(lo.y); a[mt][3] = FB(hi.y);
        }
#pragma unroll
        for (int nt = 0; nt < 4; nt++) {
            float2 bf = *(const float2*)&Bs_[(wn * 32 + nt * 8 + g) * GST + ko];
            b[nt][0] = FB(bf.x); b[nt][1] = FB(bf.y);
        }
#pragma unroll
        for (int mt = 0; mt < 2; mt++)
#pragma unroll
            for (int nt = 0; nt < 4; nt++)
                mma_tf32(c[mt][nt], a[mt][0], a[mt][1], a[mt][2], a[mt][3],
                         b[nt][0], b[nt][1]);
    }
}

__global__ __launch_bounds__(512, 2) void gemm_kernel(
    const float* __restrict__ bias, float* __restrict__ out, int mode)
{
    extern __shared__ float smf[];
    float* As = smf;
    float* Bs = smf + NSTG * STGF;

    const int t    = threadIdx.x;
    const int lane = t & 31;
    const int wp   = t >> 5;
    const int g    = lane >> 2;
    const int tg   = lane & 3;
    const int wm   = wp & 3;
    const int wn   = wp >> 2;
    const int m0   = blockIdx.y * 128;
    const int n0   = blockIdx.x * 128;

    const float* A = (mode == 1) ? (const float*)g_AO : (const float*)g_X;
    const float* B = (mode == 1) ? (const float*)g_Wo : (const float*)g_Wq;

    const int row = t >> 2;
    const int kq  = (t & 3) * 4;
    const float* Ag = A + (size_t)(m0 + row) * 1024 + kq;
    const float* Bg = B + (size_t)(n0 + row) * 1024 + kq;
    const unsigned aOff = smem_u32(As) + (unsigned)(row * GST + kq) * 4u;
    const unsigned bOff = smem_u32(Bs) + (unsigned)(row * GST + kq) * 4u;

#pragma unroll
    for (int s = 0; s < 3; s++) {
        const unsigned so = (unsigned)(s * STGF) * 4u;
        cp16(aOff + so, Ag + s * 16);
        cp16(bOff + so, Bg + s * 16);
        CP_COMMIT();
    }

    float c[2][4][4] = {};

    for (int it = 0; it < GNIT; it++) {
        CP_WAIT2();
        __syncthreads();
        if (it + 3 < GNIT) {
            const unsigned so = (unsigned)(((it + 3) & 3) * STGF) * 4u;
            cp16(aOff + so, Ag + (it + 3) * 16);
            cp16(bOff + so, Bg + (it + 3) * 16);
        }
        CP_COMMIT();
        const int cs = (it & 3) * STGF;
        g_mma_tile(As + cs, Bs + cs, c, wm, wn, g, tg);
    }

    if (mode == 0) {
        // scatter tf32-rounded Q/K/V (NATURAL layout for attention)
#pragma unroll
        for (int mt = 0; mt < 2; mt++) {
#pragma unroll
            for (int nt = 0; nt < 4; nt++) {
                int col  = n0 + wn * 32 + nt * 8 + tg * 2;
                int part = col >> 10;
                int h    = (col >> 6) & 15;
                int d    = col & 63;
                float* Tp = (part == 0) ? g_Q : (part == 1) ? g_K : g_V;
                int m  = m0 + wm * 32 + mt * 16 + g;
                int b  = m >> 11, n = m & 2047;
                *(float2*)&Tp[(((size_t)(b * HEADS + h)) * SEQ + n) * DHEAD + d] =
                    make_float2(f2tf(c[mt][nt][0]), f2tf(c[mt][nt][1]));
                int m2 = m + 8;
                int b2 = m2 >> 11, n2 = m2 & 2047;
                *(float2*)&Tp[(((size_t)(b2 * HEADS + h)) * SEQ + n2) * DHEAD + d] =
                    make_float2(f2tf(c[mt][nt][2]), f2tf(c[mt][nt][3]));
            }
        }
    } else {
#pragma unroll
        for (int mt = 0; mt < 2; mt++) {
#pragma unroll
            for (int nt = 0; nt < 4; nt++) {
                int col = n0 + wn * 32 + nt * 8 + tg * 2;
                float bx = bias[col], by = bias[col + 1];
                int m = m0 + wm * 32 + mt * 16 + g;
                *(float2*)&out[(size_t)m * DSEQ + col] =
                    make_float2(c[mt][nt][0] + bx, c[mt][nt][1] + by);
                *(float2*)&out[(size_t)(m + 8) * DSEQ + col] =
                    make_float2(c[mt][nt][2] + bx, c[mt][nt][3] + by);
            }
        }
    }
}

// ---------------------------------------------------------------------
// Flash attention (round-14, best measured): Q hoisted to registers,
// single-buffer K/V with split waits. ONLY change: epilogue writes g_AO
// with PERMUTED k-columns (pairs at stride 2) for out_gemm.
// ---------------------------------------------------------------------
#define AQT 68
#define AVT 72
#define ATTN_FLOATS (64*AQT + 64*AVT + 128*AQT)
#define ATTN_SMEM_BYTES (ATTN_FLOATS * 4)   // 70656

__global__ __launch_bounds__(128, 2) void attn_kernel() {
    extern __shared__ float sm[];
    float* Ks = sm;                          // 64*AQT  [j][d]
    float* Vs = sm + 64 * AQT;               // 64*AVT  [j][d]
    float* Ps = sm + 64 * AQT + 64 * AVT;    // 128*AQT [m][j]

    const int t    = threadIdx.x;
    const int lane = t & 31;
    const int wp   = t >> 5;
    const int g    = lane >> 2;
    const int tg   = lane & 3;
    const int bh   = blockIdx.y;
    const int q0   = blockIdx.x * 128;

    const size_t base = (size_t)bh * SEQ * DHEAD;
    const float* Qg = g_Q + base;
    const float* Kg = g_K + base;
    const float* Vg = g_V + base;

    const int lj = t >> 1;
    const int lh = (t & 1) * 32;
    const unsigned kDst = smem_u32(Ks) + (unsigned)(lj * AQT + lh) * 4u;
    const unsigned vDst = smem_u32(Vs) + (unsigned)(lj * AVT + lh) * 4u;
    const float* kSrc = Kg + (size_t)lj * DHEAD + lh;
    const float* vSrc = Vg + (size_t)lj * DHEAD + lh;

#pragma unroll
    for (int q = 0; q < 8; q++) cp16(kDst + q * 16u, kSrc + q * 4);
    CP_COMMIT();
#pragma unroll
    for (int q = 0; q < 8; q++) cp16(vDst + q * 16u, vSrc + q * 4);
    CP_COMMIT();

    // hoist Q fragments into registers (loop-invariant)
    unsigned qa[2][8][4];
#pragma unroll
    for (int mt = 0; mt < 2; mt++) {
        const float* r0 = Qg + (size_t)(q0 + wp * 32 + mt * 16 + g) * DHEAD;
        const float* r1 = r0 + 8 * DHEAD;
#pragma unroll
        for (int kk = 0; kk < 8; kk++) {
            const int k = kk * 8;
            qa[mt][kk][0] = FB(r0[k + tg] * 0.125f);
            qa[mt][kk][1] = FB(r1[k + tg] * 0.125f);
            qa[mt][kk][2] = FB(r0[k + tg + 4] * 0.125f);
            qa[mt][kk][3] = FB(r1[k + tg + 4] * 0.125f);
        }
    }

    float mi[4] = {-1e30f, -1e30f, -1e30f, -1e30f};
    float li[4] = {0.f, 0.f, 0.f, 0.f};
    float of[2][8][4] = {};

    for (int i = 0; i < SEQ / 64; i++) {
        CP_WAIT1();          // K_i complete
        __syncthreads();     // K_i visible

        // S = Q K^T
        float sc[2][8][4] = {};
#pragma unroll
        for (int kk = 0; kk < 8; kk++) {
            const int k = kk * 8;
#pragma unroll
            for (int nt = 0; nt < 8; nt++) {
                const float* bp = &Ks[(nt * 8 + g) * AQT + k + tg];
                unsigned b0 = FB(bp[0]), b1 = FB(bp[4]);
                mma_tf32(sc[0][nt], qa[0][kk][0], qa[0][kk][1], qa[0][kk][2], qa[0][kk][3], b0, b1);
                mma_tf32(sc[1][nt], qa[1][kk][0], qa[1][kk][1], qa[1][kk][2], qa[1][kk][3], b0, b1);
            }
        }
        __syncthreads();     // all warps done reading K_i

        // issue K_{i+1}
        if (i + 1 < SEQ / 64) {
            const float* ks = kSrc + (size_t)(i + 1) * 64 * DHEAD;
#pragma unroll
            for (int q = 0; q < 8; q++) cp16(kDst + q * 16u, ks + q * 4);
        }
        CP_COMMIT();

        // online softmax
        float mx[4] = {-1e30f, -1e30f, -1e30f, -1e30f};
#pragma unroll
        for (int mt = 0; mt < 2; mt++)
#pragma unroll
            for (int nt = 0; nt < 8; nt++) {
                mx[2*mt]   = fmaxf(mx[2*mt],   fmaxf(sc[mt][nt][0], sc[mt][nt][1]));
                mx[2*mt+1] = fmaxf(mx[2*mt+1], fmaxf(sc[mt][nt][2], sc[mt][nt][3]));
            }
#pragma unroll
        for (int off = 1; off <= 2; off <<= 1)
#pragma unroll
            for (int r = 0; r < 4; r++)
                mx[r] = fmaxf(mx[r], __shfl_xor_sync(0xffffffffu, mx[r], off));
        float al[4], rs[4] = {0.f, 0.f, 0.f, 0.f};
#pragma unroll
        for (int r = 0; r < 4; r++) {
            float mn = fmaxf(mi[r], mx[r]);
            al[r] = __expf(mi[r] - mn);
            mi[r] = mn;
        }
#pragma unroll
        for (int mt = 0; mt < 2; mt++)
#pragma unroll
            for (int nt = 0; nt < 8; nt++) {
                sc[mt][nt][0] = __expf(sc[mt][nt][0] - mi[2*mt]);
                sc[mt][nt][1] = __expf(sc[mt][nt][1] - mi[2*mt]);
                sc[mt][nt][2] = __expf(sc[mt][nt][2] - mi[2*mt+1]);
                sc[mt][nt][3] = __expf(sc[mt][nt][3] - mi[2*mt+1]);
                rs[2*mt]   += sc[mt][nt][0] + sc[mt][nt][1];
                rs[2*mt+1] += sc[mt][nt][2] + sc[mt][nt][3];
            }
#pragma unroll
        for (int off = 1; off <= 2; off <<= 1)
#pragma unroll
            for (int r = 0; r < 4; r++)
                rs[r] += __shfl_xor_sync(0xffffffffu, rs[r], off);
#pragma unroll
        for (int r = 0; r < 4; r++) li[r] = li[r] * al[r] + rs[r];
#pragma unroll
        for (int mt = 0; mt < 2; mt++)
#pragma unroll
            for (int nt = 0; nt < 8; nt++) {
                of[mt][nt][0] *= al[2*mt];   of[mt][nt][1] *= al[2*mt];
                of[mt][nt][2] *= al[2*mt+1]; of[mt][nt][3] *= al[2*mt+1];
            }

        CP_WAIT1();          // V_i complete
        __syncthreads();     // V_i visible

        // store P (warp-private rows)
#pragma unroll
        for (int mt = 0; mt < 2; mt++)
#pragma unroll
            for (int nt = 0; nt < 8; nt++) {
                *(float2*)&Ps[(wp * 32 + mt * 16 + g) * AQT + nt * 8 + tg * 2] =
                    make_float2(f2tf(sc[mt][nt][0]), f2tf(sc[mt][nt][1]));
                *(float2*)&Ps[(wp * 32 + mt * 16 + g + 8) * AQT + nt * 8 + tg * 2] =
                    make_float2(f2tf(sc[mt][nt][2]), f2tf(sc[mt][nt][3]));
            }
        __syncwarp();

        // O += P V
#pragma unroll
        for (int kk = 0; kk < 8; kk++) {
            const int k = kk * 8;
            unsigned a[2][4];
#pragma unroll
            for (int mt = 0; mt < 2; mt++) {
                const float* ap = &Ps[(wp * 32 + mt * 16 + g) * AQT + k + tg];
                a[mt][0] = FB(ap[0]);
                a[mt][1] = FB(ap[8 * AQT]);
                a[mt][2] = FB(ap[4]);
                a[mt][3] = FB(ap[8 * AQT + 4]);
            }
#pragma unroll
            for (int nt = 0; nt < 8; nt++) {
                unsigned b0 = FB(Vs[(k + tg)     * AVT + nt * 8 + g]);
                unsigned b1 = FB(Vs[(k + tg + 4) * AVT + nt * 8 + g]);
                mma_tf32(of[0][nt], a[0][0], a[0][1], a[0][2], a[0][3], b0, b1);
                mma_tf32(of[1][nt], a[1][0], a[1][1], a[1][2], a[1][3], b0, b1);
            }
        }
        __syncthreads();     // all warps done reading V_i

        // issue V_{i+1}
        if (i + 1 < SEQ / 64) {
            const float* vs = vSrc + (size_t)(i + 1) * 64 * DHEAD;
#pragma unroll
            for (int q = 0; q < 8; q++) cp16(vDst + q * 16u, vs + q * 4);
        }
        CP_COMMIT();
    }

    // epilogue: write g_AO tf32-rounded, PERMUTED k-cols for out_gemm
    const int b = bh >> 4;
    const int h = bh & 15;
#pragma unroll
    for (int mt = 0; mt < 2; mt++) {
        const float inv0 = 1.0f / li[2*mt];
        const float inv1 = 1.0f / li[2*mt+1];
        const int row0 = q0 + wp * 32 + mt * 16 + g;
#pragma unroll
        for (int nt = 0; nt < 8; nt++) {
            int d  = nt * 8 + tg * 2;
            int p0 = cperm8(d);                 // pos of d; d+1 lands at p0+2
            float* dst0 = &g_AO[((size_t)(b * SEQ + row0)) * DINNER + h * 64];
            float* dst1 = &g_AO[((size_t)(b * SEQ + row0 + 8)) * DINNER + h * 64];
            dst0[p0]     = f2tf(of[mt][nt][0] * inv0);
            dst0[p0 + 2] = f2tf(of[mt][nt][1] * inv0);
            dst1[p0]     = f2tf(of[mt][nt][2] * inv1);
            dst1[p0 + 2] = f2tf(of[mt][nt][3] * inv1);
        }
    }
}

// ---------------------------------------------------------------------
extern "C" void kernel_launch(void* const* d_in, const int* in_sizes, int n_in,
                              void* d_out, int out_size) {
    const float* x     = (const float*)d_in[0];
    const float* w_qkv = (const float*)d_in[1];
    const float* w_out = (const float*)d_in[2];
    const float* b_out = (const float*)d_in[3];
    float* out = (float*)d_out;

    cudaFuncSetAttribute(gemm_kernel, cudaFuncAttributeMaxDynamicSharedMemorySize,
                         GEMM_SMEM_BYTES);
    cudaFuncSetAttribute(attn_kernel, cudaFuncAttributeMaxDynamicSharedMemorySize,
                         ATTN_SMEM_BYTES);

    preconvert<<<(PRECONV_ELEMS / 4 + 255) / 256, 256>>>(x, w_qkv, w_out);
    gemm_kernel<<<dim3(NQKV / 128, MROWS / 128), 512, GEMM_SMEM_BYTES>>>(nullptr, nullptr, 0);
    attn_kernel<<<dim3(SEQ / 128, BATCH * HEADS), 128, ATTN_SMEM_BYTES>>>();
    gemm_kernel<<<dim3(DSEQ / 128, MROWS / 128), 512, GEMM_SMEM_BYTES>>>(b_out, out, 1);
}

// round 17
// speedup vs baseline: 1.0713x; 1.0126x over previous
#include <cuda_runtime.h>
#include <cstdint>

#define BATCH 4
#define SEQ   2048
#define DSEQ  1024
#define HEADS 16
#define DHEAD 64
#define DINNER 1024
#define MROWS (BATCH*SEQ)   // 8192
#define NQKV  (3*DINNER)    // 3072

// Scratch (allocation-free: __device__ globals)
__device__ float g_Q[BATCH * HEADS * SEQ * DHEAD];   // natural d
__device__ float g_K[BATCH * HEADS * SEQ * DHEAD];   // PERMUTED d-cols
__device__ float g_V[BATCH * HEADS * SEQ * DHEAD];   // natural d
__device__ float g_AO[MROWS * DINNER];               // PERMUTED k-cols
// tf32-pre-rounded, column-PERMUTED operand copies
__device__ float g_X[MROWS * DSEQ];
__device__ float g_Wq[NQKV * DSEQ];
__device__ float g_Wo[DSEQ * DINNER];

__device__ __forceinline__ float f2tf(float f) {
    unsigned u;
    asm("cvt.rna.tf32.f32 %0, %1;" : "=r"(u) : "f"(f));
    return __uint_as_float(u);
}
__device__ __forceinline__ void mma_tf32(float c[4],
                                         unsigned a0, unsigned a1, unsigned a2, unsigned a3,
                                         unsigned b0, unsigned b1) {
    asm volatile(
        "mma.sync.aligned.m16n8k8.row.col.f32.tf32.tf32.f32 "
        "{%0,%1,%2,%3},{%4,%5,%6,%7},{%8,%9},{%0,%1,%2,%3};"
        : "+f"(c[0]), "+f"(c[1]), "+f"(c[2]), "+f"(c[3])
        : "r"(a0), "r"(a1), "r"(a2), "r"(a3), "r"(b0), "r"(b1));
}
#define FB(x) __float_as_uint(x)

__device__ __forceinline__ unsigned smem_u32(const void* p) {
    unsigned a;
    asm("{ .reg .u64 t; cvta.to.shared.u64 t, %1; cvt.u32.u64 %0, t; }"
        : "=r"(a) : "l"(p));
    return a;
}
__device__ __forceinline__ void cp16(unsigned dst, const float* src) {
    asm volatile("cp.async.cg.shared.global [%0], [%1], 16;"
                 :: "r"(dst), "l"(src) : "memory");
}
#define CP_COMMIT() asm volatile("cp.async.commit_group;" ::: "memory")
#define CP_WAIT2()  asm volatile("cp.async.wait_group 2;" ::: "memory")
#define CP_WAIT1()  asm volatile("cp.async.wait_group 1;" ::: "memory")

// fragment-pair permutation within each 8-col group:
// logical c -> (c & ~7) | 2*(c&3) | ((c>>2)&1). Pairs (c, c+4) adjacent.
__device__ __forceinline__ int cperm8(int c) {
    return (c & ~7) | (((c & 3) << 1) | ((c >> 2) & 1));
}

// ---------------------------------------------------------------------
// Pre-convert inputs to tf32-rounded, column-permuted copies.
// ---------------------------------------------------------------------
__global__ __launch_bounds__(256) void preconvert(const float* __restrict__ x,
                                                  const float* __restrict__ wq,
                                                  const float* __restrict__ wo) {
    const int idx = (blockIdx.x * 256 + threadIdx.x) * 4;
    const int NX = MROWS * DSEQ, NQ = NQKV * DSEQ, NO = DSEQ * DINNER;
    const float* src; float* dst; int i;
    if (idx < NX)            { src = x;  dst = g_X;  i = idx; }
    else if (idx < NX + NQ)  { src = wq; dst = g_Wq; i = idx - NX; }
    else if (idx < NX + NQ + NO) { src = wo; dst = g_Wo; i = idx - NX - NQ; }
    else return;
    float4 v = *(const float4*)(src + i);
    const int base = (i & ~7) | ((i >> 2) & 1);
    dst[base + 0] = f2tf(v.x);
    dst[base + 2] = f2tf(v.y);
    dst[base + 4] = f2tf(v.z);
    dst[base + 6] = f2tf(v.w);
}
#define PRECONV_ELEMS (MROWS * DSEQ + NQKV * DSEQ + DSEQ * DINNER)

// ---------------------------------------------------------------------
// GEMM (round-16, verified): BM=BN=128, BK=16, 512 thr, warp tile 32x32,
// GST=24 permuted cols -> all fragment loads LDS.64. 4-stage cp.async.
// mode 0: g_X @ g_Wq^T -> Q/V natural, K PERMUTED d-cols.
// mode 1: g_AO @ g_Wo^T + bias -> out.
// ---------------------------------------------------------------------
#define GST 24
#define NSTG 4
#define STGF (128 * GST)
#define GNIT 64
#define GEMM_SMEM_BYTES (2 * NSTG * STGF * 4)   // 98304

__device__ __forceinline__ void g_mma_tile(const float* As_, const float* Bs_,
                                           float c[2][4][4],
                                           int wm, int wn, int g, int tg) {
#pragma unroll
    for (int kk = 0; kk < 2; kk++) {
        const int ko = kk * 8 + 2 * tg;
        unsigned a[2][4], b[4][2];
#pragma unroll
        for (int mt = 0; mt < 2; mt++) {
            const float* ap = &As_[(wm * 32 + mt * 16 + g) * GST + ko];
            float2 lo = *(const float2*)ap;
            float2 hi = *(const float2*)(ap + 8 * GST);
            a[mt][0] = FB(lo.x); a[mt][1] = FB(hi.x);
            a[mt][2] = FB(lo.y); a[mt][3] = FB(hi.y);
        }
#pragma unroll
        for (int nt = 0; nt < 4; nt++) {
            float2 bf = *(const float2*)&Bs_[(wn * 32 + nt * 8 + g) * GST + ko];
            b[nt][0] = FB(bf.x); b[nt][1] = FB(bf.y);
        }
#pragma unroll
        for (int mt = 0; mt < 2; mt++)
#pragma unroll
            for (int nt = 0; nt < 4; nt++)
                mma_tf32(c[mt][nt], a[mt][0], a[mt][1], a[mt][2], a[mt][3],
                         b[nt][0], b[nt][1]);
    }
}

__global__ __launch_bounds__(512, 2) void gemm_kernel(
    const float* __restrict__ bias, float* __restrict__ out, int mode)
{
    extern __shared__ float smf[];
    float* As = smf;
    float* Bs = smf + NSTG * STGF;

    const int t    = threadIdx.x;
    const int lane = t & 31;
    const int wp   = t >> 5;
    const int g    = lane >> 2;
    const int tg   = lane & 3;
    const int wm   = wp & 3;
    const int wn   = wp >> 2;
    const int m0   = blockIdx.y * 128;
    const int n0   = blockIdx.x * 128;

    const float* A = (mode == 1) ? (const float*)g_AO : (const float*)g_X;
    const float* B = (mode == 1) ? (const float*)g_Wo : (const float*)g_Wq;

    const int row = t >> 2;
    const int kq  = (t & 3) * 4;
    const float* Ag = A + (size_t)(m0 + row) * 1024 + kq;
    const float* Bg = B + (size_t)(n0 + row) * 1024 + kq;
    const unsigned aOff = smem_u32(As) + (unsigned)(row * GST + kq) * 4u;
    const unsigned bOff = smem_u32(Bs) + (unsigned)(row * GST + kq) * 4u;

#pragma unroll
    for (int s = 0; s < 3; s++) {
        const unsigned so = (unsigned)(s * STGF) * 4u;
        cp16(aOff + so, Ag + s * 16);
        cp16(bOff + so, Bg + s * 16);
        CP_COMMIT();
    }

    float c[2][4][4] = {};

    for (int it = 0; it < GNIT; it++) {
        CP_WAIT2();
        __syncthreads();
        if (it + 3 < GNIT) {
            const unsigned so = (unsigned)(((it + 3) & 3) * STGF) * 4u;
            cp16(aOff + so, Ag + (it + 3) * 16);
            cp16(bOff + so, Bg + (it + 3) * 16);
        }
        CP_COMMIT();
        const int cs = (it & 3) * STGF;
        g_mma_tile(As + cs, Bs + cs, c, wm, wn, g, tg);
    }

    if (mode == 0) {
#pragma unroll
        for (int mt = 0; mt < 2; mt++) {
#pragma unroll
            for (int nt = 0; nt < 4; nt++) {
                int col  = n0 + wn * 32 + nt * 8 + tg * 2;
                int part = col >> 10;
                int h    = (col >> 6) & 15;
                int d    = col & 63;
                float* Tp = (part == 0) ? g_Q : (part == 1) ? g_K : g_V;
                int m  = m0 + wm * 32 + mt * 16 + g;
                int b  = m >> 11, n = m & 2047;
                size_t o1 = (((size_t)(b * HEADS + h)) * SEQ + n) * DHEAD;
                int m2 = m + 8;
                int b2 = m2 >> 11, n2 = m2 & 2047;
                size_t o2 = (((size_t)(b2 * HEADS + h)) * SEQ + n2) * DHEAD;
                if (part == 1) {
                    // K: permuted d-cols (pair lands at p0, p0+2)
                    int p0 = cperm8(d);
                    Tp[o1 + p0]     = f2tf(c[mt][nt][0]);
                    Tp[o1 + p0 + 2] = f2tf(c[mt][nt][1]);
                    Tp[o2 + p0]     = f2tf(c[mt][nt][2]);
                    Tp[o2 + p0 + 2] = f2tf(c[mt][nt][3]);
                } else {
                    *(float2*)&Tp[o1 + d] =
                        make_float2(f2tf(c[mt][nt][0]), f2tf(c[mt][nt][1]));
                    *(float2*)&Tp[o2 + d] =
                        make_float2(f2tf(c[mt][nt][2]), f2tf(c[mt][nt][3]));
                }
            }
        }
    } else {
#pragma unroll
        for (int mt = 0; mt < 2; mt++) {
#pragma unroll
            for (int nt = 0; nt < 4; nt++) {
                int col = n0 + wn * 32 + nt * 8 + tg * 2;
                float bx = bias[col], by = bias[col + 1];
                int m = m0 + wm * 32 + mt * 16 + g;
                *(float2*)&out[(size_t)m * DSEQ + col] =
                    make_float2(c[mt][nt][0] + bx, c[mt][nt][1] + by);
                *(float2*)&out[(size_t)(m + 8) * DSEQ + col] =
                    make_float2(c[mt][nt][2] + bx, c[mt][nt][3] + by);
            }
        }
    }
}

// ---------------------------------------------------------------------
// Flash attention (round-16 structure). K arrives PERMUTED -> S-phase
// B-frags are single LDS.64 from stride-72 Ks (conflict-free: per phase
// word offsets 72g+2tg mod 32 = {0-6},{8-14},{16-22},{24-30}).
// Q hoisted to registers (natural). Epilogue writes g_AO permuted.
// ---------------------------------------------------------------------
#define KST 72
#define AVT 72
#define PST 68
#define ATTN_FLOATS (64*KST + 64*AVT + 128*PST)
#define ATTN_SMEM_BYTES (ATTN_FLOATS * 4)   // 71680

__global__ __launch_bounds__(128, 2) void attn_kernel() {
    extern __shared__ float sm[];
    float* Ks = sm;                          // 64*KST  [j][perm d]
    float* Vs = sm + 64 * KST;               // 64*AVT  [j][d]
    float* Ps = sm + 64 * KST + 64 * AVT;    // 128*PST [m][j]

    const int t    = threadIdx.x;
    const int lane = t & 31;
    const int wp   = t >> 5;
    const int g    = lane >> 2;
    const int tg   = lane & 3;
    const int bh   = blockIdx.y;
    const int q0   = blockIdx.x * 128;

    const size_t base = (size_t)bh * SEQ * DHEAD;
    const float* Qg = g_Q + base;
    const float* Kg = g_K + base;
    const float* Vg = g_V + base;

    const int lj = t >> 1;
    const int lh = (t & 1) * 32;
    const unsigned kDst = smem_u32(Ks) + (unsigned)(lj * KST + lh) * 4u;
    const unsigned vDst = smem_u32(Vs) + (unsigned)(lj * AVT + lh) * 4u;
    const float* kSrc = Kg + (size_t)lj * DHEAD + lh;
    const float* vSrc = Vg + (size_t)lj * DHEAD + lh;

#pragma unroll
    for (int q = 0; q < 8; q++) cp16(kDst + q * 16u, kSrc + q * 4);
    CP_COMMIT();
#pragma unroll
    for (int q = 0; q < 8; q++) cp16(vDst + q * 16u, vSrc + q * 4);
    CP_COMMIT();

    // hoist Q fragments into registers (g_Q natural; indices unchanged)
    unsigned qa[2][8][4];
#pragma unroll
    for (int mt = 0; mt < 2; mt++) {
        const float* r0 = Qg + (size_t)(q0 + wp * 32 + mt * 16 + g) * DHEAD;
        const float* r1 = r0 + 8 * DHEAD;
#pragma unroll
        for (int kk = 0; kk < 8; kk++) {
            const int k = kk * 8;
            qa[mt][kk][0] = FB(r0[k + tg] * 0.125f);
            qa[mt][kk][1] = FB(r1[k + tg] * 0.125f);
            qa[mt][kk][2] = FB(r0[k + tg + 4] * 0.125f);
            qa[mt][kk][3] = FB(r1[k + tg + 4] * 0.125f);
        }
    }

    float mi[4] = {-1e30f, -1e30f, -1e30f, -1e30f};
    float li[4] = {0.f, 0.f, 0.f, 0.f};
    float of[2][8][4] = {};

    for (int i = 0; i < SEQ / 64; i++) {
        CP_WAIT1();          // K_i complete
        __syncthreads();     // K_i visible

        // S = Q K^T  (K B-frag = 1 LDS.64: physical pair = logical k+tg, k+tg+4)
        float sc[2][8][4] = {};
#pragma unroll
        for (int kk = 0; kk < 8; kk++) {
            const int ko = kk * 8 + 2 * tg;
#pragma unroll
            for (int nt = 0; nt < 8; nt++) {
                float2 kf = *(const float2*)&Ks[(nt * 8 + g) * KST + ko];
                unsigned b0 = FB(kf.x), b1 = FB(kf.y);
                mma_tf32(sc[0][nt], qa[0][kk][0], qa[0][kk][1], qa[0][kk][2], qa[0][kk][3], b0, b1);
                mma_tf32(sc[1][nt], qa[1][kk][0], qa[1][kk][1], qa[1][kk][2], qa[1][kk][3], b0, b1);
            }
        }
        __syncthreads();     // all warps done reading K_i

        // issue K_{i+1}
        if (i + 1 < SEQ / 64) {
            const float* ks = kSrc + (size_t)(i + 1) * 64 * DHEAD;
#pragma unroll
            for (int q = 0; q < 8; q++) cp16(kDst + q * 16u, ks + q * 4);
        }
        CP_COMMIT();

        // online softmax
        float mx[4] = {-1e30f, -1e30f, -1e30f, -1e30f};
#pragma unroll
        for (int mt = 0; mt < 2; mt++)
#pragma unroll
            for (int nt = 0; nt < 8; nt++) {
                mx[2*mt]   = fmaxf(mx[2*mt],   fmaxf(sc[mt][nt][0], sc[mt][nt][1]));
                mx[2*mt+1] = fmaxf(mx[2*mt+1], fmaxf(sc[mt][nt][2], sc[mt][nt][3]));
            }
#pragma unroll
        for (int off = 1; off <= 2; off <<= 1)
#pragma unroll
            for (int r = 0; r < 4; r++)
                mx[r] = fmaxf(mx[r], __shfl_xor_sync(0xffffffffu, mx[r], off));
        float al[4], rs[4] = {0.f, 0.f, 0.f, 0.f};
#pragma unroll
        for (int r = 0; r < 4; r++) {
            float mn = fmaxf(mi[r], mx[r]);
            al[r] = __expf(mi[r] - mn);
            mi[r] = mn;
        }
#pragma unroll
        for (int mt = 0; mt < 2; mt++)
#pragma unroll
            for (int nt = 0; nt < 8; nt++) {
                sc[mt][nt][0] = __expf(sc[mt][nt][0] - mi[2*mt]);
                sc[mt][nt][1] = __expf(sc[mt][nt][1] - mi[2*mt]);
                sc[mt][nt][2] = __expf(sc[mt][nt][2] - mi[2*mt+1]);
                sc[mt][nt][3] = __expf(sc[mt][nt][3] - mi[2*mt+1]);
                rs[2*mt]   += sc[mt][nt][0] + sc[mt][nt][1];
                rs[2*mt+1] += sc[mt][nt][2] + sc[mt][nt][3];
            }
#pragma unroll
        for (int off = 1; off <= 2; off <<= 1)
#pragma unroll
            for (int r = 0; r < 4; r++)
                rs[r] += __shfl_xor_sync(0xffffffffu, rs[r], off);
#pragma unroll
        for (int r = 0; r < 4; r++) li[r] = li[r] * al[r] + rs[r];
#pragma unroll
        for (int mt = 0; mt < 2; mt++)
#pragma unroll
            for (int nt = 0; nt < 8; nt++) {
                of[mt][nt][0] *= al[2*mt];   of[mt][nt][1] *= al[2*mt];
                of[mt][nt][2] *= al[2*mt+1]; of[mt][nt][3] *= al[2*mt+1];
            }

        CP_WAIT1();          // V_i complete
        __syncthreads();     // V_i visible

        // store P (warp-private rows)
#pragma unroll
        for (int mt = 0; mt < 2; mt++)
#pragma unroll
            for (int nt = 0; nt < 8; nt++) {
                *(float2*)&Ps[(wp * 32 + mt * 16 + g) * PST + nt * 8 + tg * 2] =
                    make_float2(f2tf(sc[mt][nt][0]), f2tf(sc[mt][nt][1]));
                *(float2*)&Ps[(wp * 32 + mt * 16 + g + 8) * PST + nt * 8 + tg * 2] =
                    make_float2(f2tf(sc[mt][nt][2]), f2tf(sc[mt][nt][3]));
            }
        __syncwarp();

        // O += P V
#pragma unroll
        for (int kk = 0; kk < 8; kk++) {
            const int k = kk * 8;
            unsigned a[2][4];
#pragma unroll
            for (int mt = 0; mt < 2; mt++) {
                const float* ap = &Ps[(wp * 32 + mt * 16 + g) * PST + k + tg];
                a[mt][0] = FB(ap[0]);
                a[mt][1] = FB(ap[8 * PST]);
                a[mt][2] = FB(ap[4]);
                a[mt][3] = FB(ap[8 * PST + 4]);
            }
#pragma unroll
            for (int nt = 0; nt < 8; nt++) {
                unsigned b0 = FB(Vs[(k + tg)     * AVT + nt * 8 + g]);
                unsigned b1 = FB(Vs[(k + tg + 4) * AVT + nt * 8 + g]);
                mma_tf32(of[0][nt], a[0][0], a[0][1], a[0][2], a[0][3], b0, b1);
                mma_tf32(of[1][nt], a[1][0], a[1][1], a[1][2], a[1][3], b0, b1);
            }
        }
        __syncthreads();     // all warps done reading V_i

        // issue V_{i+1}
        if (i + 1 < SEQ / 64) {
            const float* vs = vSrc + (size_t)(i + 1) * 64 * DHEAD;
#pragma unroll
            for (int q = 0; q < 8; q++) cp16(vDst + q * 16u, vs + q * 4);
        }
        CP_COMMIT();
    }

    // epilogue: write g_AO tf32-rounded, PERMUTED k-cols for out_gemm
    const int b = bh >> 4;
    const int h = bh & 15;
#pragma unroll
    for (int mt = 0; mt < 2; mt++) {
        const float inv0 = 1.0f / li[2*mt];
        const float inv1 = 1.0f / li[2*mt+1];
        const int row0 = q0 + wp * 32 + mt * 16 + g;
#pragma unroll
        for (int nt = 0; nt < 8; nt++) {
            int d  = nt * 8 + tg * 2;
            int p0 = cperm8(d);
            float* dst0 = &g_AO[((size_t)(b * SEQ + row0)) * DINNER + h * 64];
            float* dst1 = &g_AO[((size_t)(b * SEQ + row0 + 8)) * DINNER + h * 64];
            dst0[p0]     = f2tf(of[mt][nt][0] * inv0);
            dst0[p0 + 2] = f2tf(of[mt][nt][1] * inv0);
            dst1[p0]     = f2tf(of[mt][nt][2] * inv1);
            dst1[p0 + 2] = f2tf(of[mt][nt][3] * inv1);
        }
    }
}

// ---------------------------------------------------------------------
extern "C" void kernel_launch(void* const* d_in, const int* in_sizes, int n_in,
                              void* d_out, int out_size) {
    const float* x     = (const float*)d_in[0];
    const float* w_qkv = (const float*)d_in[1];
    const float* w_out = (const float*)d_in[2];
    const float* b_out = (const float*)d_in[3];
    float* out = (float*)d_out;

    cudaFuncSetAttribute(gemm_kernel, cudaFuncAttributeMaxDynamicSharedMemorySize,
                         GEMM_SMEM_BYTES);
    cudaFuncSetAttribute(attn_kernel, cudaFuncAttributeMaxDynamicSharedMemorySize,
                         ATTN_SMEM_BYTES);

    preconvert<<<(PRECONV_ELEMS / 4 + 255) / 256, 256>>>(x, w_qkv, w_out);
    gemm_kernel<<<dim3(NQKV / 128, MROWS / 128), 512, GEMM_SMEM_BYTES>>>(nullptr, nullptr, 0);
    attn_kernel<<<dim3(SEQ / 128, BATCH * HEADS), 128, ATTN_SMEM_BYTES>>>();
    gemm_kernel<<<dim3(DSEQ / 128, MROWS / 128), 512, GEMM_SMEM_BYTES>>>(b_out, out, 1);
}